// round 11
// baseline (speedup 1.0000x reference)
#include <cuda_runtime.h>
#include <cuda_fp16.h>
#include <cstdint>

#define NUM_USERS 100000
#define NUM_ITEMS 100000
#define N_NODES   200000
#define EMB       64
#define N_EDGES   3200000
#define VEC_TOTAL (N_NODES * (EMB / 4))   // 3.2M: float4 slots in ego tensor
#define CSR_CAP   (N_EDGES + N_NODES)     // even-padded rows: <= E + V entries
#define SCAN_BLK  1024
#define N_SCAN_BLKS ((N_NODES + SCAN_BLK - 1) / SCAN_BLK)   // 196

// ---------------------------------------------------------------------------
// Static device scratch (allocation-free per harness rules).
// fp16 node buffers, 16B-aligned rows: row = 8 x uint4 (128B).
// ---------------------------------------------------------------------------
__device__ __align__(16) uint4 g_src[(size_t)N_NODES * 8];  // fp16 ego
__device__ __align__(16) uint4 g_l1h[(size_t)N_NODES * 8];  // fp16 layer-1 out
__device__ __align__(16) uint4 g_l2h[(size_t)N_NODES * 8];  // fp16 layer-2 out
__device__ __align__(16) int2  g_csr[CSR_CAP];  // (col, w-bits), rows even-padded
__device__ int2 g_hdr[N_NODES];                 // (rowstart, cnt) packed
__device__ int  g_cnt[N_NODES];
__device__ int  g_rowstart[N_NODES];
__device__ int  g_cursor[N_NODES];
__device__ int  g_blksums[N_SCAN_BLKS];

// ---------------------------------------------------------------------------
// Zero the degree counters (must precede k_initcount's atomics).
// ---------------------------------------------------------------------------
__global__ void k_zero()
{
    int i = blockIdx.x * blockDim.x + threadIdx.x;
    if (i < N_NODES) g_cnt[i] = 0;
}

// ---------------------------------------------------------------------------
// Fused: fp16-convert ego embeddings AND count edge degrees (both 3.2M-wide).
// The conversion's streaming traffic hides under the count's atomic latency.
// ---------------------------------------------------------------------------
__global__ void __launch_bounds__(256)
k_initcount(const float4* __restrict__ user, const float4* __restrict__ item,
            const int* __restrict__ row)
{
    int i = blockIdx.x * blockDim.x + threadIdx.x;
    if (i < VEC_TOTAL) {
        const int usz = NUM_USERS * (EMB / 4);
        float4 v = (i < usz) ? __ldg(user + i) : __ldg(item + (i - usz));
        __half2 h0 = __floats2half2_rn(v.x, v.y);
        __half2 h1 = __floats2half2_rn(v.z, v.w);
        uint2 u;
        u.x = *reinterpret_cast<unsigned*>(&h0);
        u.y = *reinterpret_cast<unsigned*>(&h1);
        reinterpret_cast<uint2*>(g_src)[i] = u;
    }
    if (i < N_EDGES) {
        atomicAdd(&g_cnt[__ldg(row + i)], 1);
    }
}

// ---------------------------------------------------------------------------
// Scan of PADDED counts p_i = (c_i+1)&~1 (rows stay 16B-aligned in g_csr).
// ---------------------------------------------------------------------------
__global__ void __launch_bounds__(SCAN_BLK) k_scan1()
{
    __shared__ int s[SCAN_BLK];
    int t = threadIdx.x;
    int i = blockIdx.x * SCAN_BLK + t;
    int c = (i < N_NODES) ? g_cnt[i] : 0;
    int v = (c + 1) & ~1;                 // padded degree
    s[t] = v;
    __syncthreads();
    #pragma unroll
    for (int off = 1; off < SCAN_BLK; off <<= 1) {
        int add = (t >= off) ? s[t - off] : 0;
        __syncthreads();
        s[t] += add;
        __syncthreads();
    }
    if (i < N_NODES) g_rowstart[i] = s[t] - v;           // exclusive in-block
    if (t == SCAN_BLK - 1) g_blksums[blockIdx.x] = s[t]; // block total
}

__global__ void __launch_bounds__(256) k_scan2()
{
    __shared__ int s[256];
    int t = threadIdx.x;
    int v = (t < N_SCAN_BLKS) ? g_blksums[t] : 0;
    s[t] = v;
    __syncthreads();
    #pragma unroll
    for (int off = 1; off < 256; off <<= 1) {
        int add = (t >= off) ? s[t - off] : 0;
        __syncthreads();
        s[t] += add;
        __syncthreads();
    }
    if (t < N_SCAN_BLKS) g_blksums[t] = s[t] - v;        // exclusive
}

// Finalize offsets; init cursors; pack (start,cnt); write w=0 pad slots.
__global__ void k_scan3()
{
    int i = blockIdx.x * blockDim.x + threadIdx.x;
    if (i >= N_NODES) return;
    int v = g_rowstart[i] + g_blksums[i >> 10];
    int c = g_cnt[i];
    g_cursor[i] = v;
    g_hdr[i]    = make_int2(v, c);
    if (c & 1) g_csr[v + c] = make_int2(0, 0);           // col=0, w=0 (harmless)
}

__global__ void __launch_bounds__(256)
k_fill(const int* __restrict__ row, const int* __restrict__ col,
       const float* __restrict__ w)
{
    int e = blockIdx.x * blockDim.x + threadIdx.x;
    if (e >= N_EDGES) return;
    int r   = __ldg(row + e);
    int pos = atomicAdd(&g_cursor[r], 1);
    g_csr[pos] = make_int2(__ldg(col + e), __float_as_int(__ldg(w + e)));
}

// ---------------------------------------------------------------------------
// Gather SpMM: 4 rows per warp, 8 lanes per row, 16B (8 fp16 dims) per lane.
//   src LDG:  1 LDG.128 warp-instr per 4 edges  (0.25 / edge)
//   meta LDG: 1 int4 (2 edges) per 8-lane quarter -> 0.125 / edge
// Total 0.375 LDG warp-instr/edge. Accumulation fp32; out fp32.
// ---------------------------------------------------------------------------
__device__ __forceinline__ void fma_edge8(float* a, uint4 u, float w)
{
    __half2 h0 = *reinterpret_cast<__half2*>(&u.x);
    __half2 h1 = *reinterpret_cast<__half2*>(&u.y);
    __half2 h2 = *reinterpret_cast<__half2*>(&u.z);
    __half2 h3 = *reinterpret_cast<__half2*>(&u.w);
    float2 f0 = __half22float2(h0);
    float2 f1 = __half22float2(h1);
    float2 f2 = __half22float2(h2);
    float2 f3 = __half22float2(h3);
    a[0] += w * f0.x; a[1] += w * f0.y;
    a[2] += w * f1.x; a[3] += w * f1.y;
    a[4] += w * f2.x; a[5] += w * f2.y;
    a[6] += w * f3.x; a[7] += w * f3.y;
}

template<int LAYER>
__global__ void __launch_bounds__(256)
k_gather(float4* __restrict__ out)
{
    int tid  = blockIdx.x * blockDim.x + threadIdx.x;
    int gw   = tid >> 5;                 // global warp
    int lane = threadIdx.x & 31;
    int quarter = lane >> 3;             // 0..3: which row in this warp
    int sub     = lane & 7;              // 0..7: 16B chunk within the row
    int row  = gw * 4 + quarter;
    if (row >= N_NODES) return;

    const uint4* __restrict__ src =
        (LAYER == 0) ? g_src : (LAYER == 1) ? g_l1h : g_l2h;

    int2 hdr = __ldg(&g_hdr[row]);
    const int start = hdr.x;
    const int pend  = start + ((hdr.y + 1) & ~1);        // padded end (even)
    const int4* csr4 = reinterpret_cast<const int4*>(g_csr);

    float a[8] = {0.f, 0.f, 0.f, 0.f, 0.f, 0.f, 0.f, 0.f};
    int j = start;

    // 8-edge batches: 4 int4 meta + 8 uint4 src loads in flight per quarter.
    for (; j + 8 <= pend; j += 8) {
        int4 m[4];
        #pragma unroll
        for (int k = 0; k < 4; ++k) m[k] = __ldg(csr4 + (j >> 1) + k);
        uint4 v[8];
        #pragma unroll
        for (int k = 0; k < 4; ++k) {
            v[2*k]   = __ldg(src + (size_t)m[k].x * 8 + sub);
            v[2*k+1] = __ldg(src + (size_t)m[k].z * 8 + sub);
        }
        #pragma unroll
        for (int k = 0; k < 4; ++k) {
            fma_edge8(a, v[2*k],   __int_as_float(m[k].y));
            fma_edge8(a, v[2*k+1], __int_as_float(m[k].w));
        }
    }
    if (j + 4 <= pend) {
        int4 m0 = __ldg(csr4 + (j >> 1) + 0);
        int4 m1 = __ldg(csr4 + (j >> 1) + 1);
        uint4 v0 = __ldg(src + (size_t)m0.x * 8 + sub);
        uint4 v1 = __ldg(src + (size_t)m0.z * 8 + sub);
        uint4 v2 = __ldg(src + (size_t)m1.x * 8 + sub);
        uint4 v3 = __ldg(src + (size_t)m1.z * 8 + sub);
        fma_edge8(a, v0, __int_as_float(m0.y));
        fma_edge8(a, v1, __int_as_float(m0.w));
        fma_edge8(a, v2, __int_as_float(m1.y));
        fma_edge8(a, v3, __int_as_float(m1.w));
        j += 4;
    }
    if (j + 2 <= pend) {
        int4 m = __ldg(csr4 + (j >> 1));
        uint4 v0 = __ldg(src + (size_t)m.x * 8 + sub);
        uint4 v1 = __ldg(src + (size_t)m.z * 8 + sub);
        fma_edge8(a, v0, __int_as_float(m.y));
        fma_edge8(a, v1, __int_as_float(m.w));
    }

    const size_t oh = (size_t)row * 8 + sub;        // fp16 buffer slot (uint4)
    const size_t of = (size_t)row * 16 + sub * 2;   // fp32 out slot (2x float4)

    if (LAYER == 0 || LAYER == 1) {
        __half2 h0 = __floats2half2_rn(a[0], a[1]);
        __half2 h1 = __floats2half2_rn(a[2], a[3]);
        __half2 h2 = __floats2half2_rn(a[4], a[5]);
        __half2 h3 = __floats2half2_rn(a[6], a[7]);
        uint4 u;
        u.x = *reinterpret_cast<unsigned*>(&h0);
        u.y = *reinterpret_cast<unsigned*>(&h1);
        u.z = *reinterpret_cast<unsigned*>(&h2);
        u.w = *reinterpret_cast<unsigned*>(&h3);
        if (LAYER == 0) {
            g_l1h[oh] = u;                               // src of L1
            out[of]     = make_float4(a[0], a[1], a[2], a[3]);  // l1 undivided
            out[of + 1] = make_float4(a[4], a[5], a[6], a[7]);
        } else {
            g_l2h[oh] = u;                               // src of L2
        }
    } else {
        float4 p0 = out[of];
        float4 p1 = out[of + 1];
        uint4  u2 = g_l2h[oh];
        __half2 h0 = *reinterpret_cast<__half2*>(&u2.x);
        __half2 h1 = *reinterpret_cast<__half2*>(&u2.y);
        __half2 h2 = *reinterpret_cast<__half2*>(&u2.z);
        __half2 h3 = *reinterpret_cast<__half2*>(&u2.w);
        float2 q0 = __half22float2(h0);
        float2 q1 = __half22float2(h1);
        float2 q2 = __half22float2(h2);
        float2 q3 = __half22float2(h3);
        const float inv3 = 1.0f / 3.0f;
        out[of] = make_float4((p0.x + q0.x + a[0]) * inv3,
                              (p0.y + q0.y + a[1]) * inv3,
                              (p0.z + q1.x + a[2]) * inv3,
                              (p0.w + q1.y + a[3]) * inv3);
        out[of + 1] = make_float4((p1.x + q2.x + a[4]) * inv3,
                                  (p1.y + q2.y + a[5]) * inv3,
                                  (p1.z + q3.x + a[6]) * inv3,
                                  (p1.w + q3.y + a[7]) * inv3);
    }
}

// ---------------------------------------------------------------------------
// Launch. Inputs (metadata order):
//   d_in[0] user_emb f32 [100000*64]   d_in[1] item_emb f32 [100000*64]
//   d_in[2] edge_w   f32 [3.2M]        d_in[3] edge_row i32   d_in[4] edge_col i32
// d_out: f32 [200000*64] = (l1+l2+l3)/3.
// ---------------------------------------------------------------------------
extern "C" void kernel_launch(void* const* d_in, const int* in_sizes, int n_in,
                              void* d_out, int out_size)
{
    const float4* user = (const float4*)d_in[0];
    const float4* item = (const float4*)d_in[1];
    const float*  ew   = (const float*)d_in[2];
    const int*    erow = (const int*)d_in[3];
    const int*    ecol = (const int*)d_in[4];
    float4*       out  = (float4*)d_out;

    const int BLK = 256;
    const int grid_nodes  = (N_NODES + BLK - 1) / BLK;            // 782
    const int grid_edges  = (N_EDGES + BLK - 1) / BLK;            // 12500
    const int grid_gather = ((N_NODES / 4) * 32 + BLK - 1) / BLK; // 6250

    // CSR build + fused fp16 conversion (once; reused by all 3 layers)
    k_zero     <<<grid_nodes, BLK>>>();
    k_initcount<<<grid_edges, BLK>>>(user, item, erow);
    k_scan1    <<<N_SCAN_BLKS, SCAN_BLK>>>();
    k_scan2    <<<1, 256>>>();
    k_scan3    <<<grid_nodes, BLK>>>();
    k_fill     <<<grid_edges, BLK>>>(erow, ecol, ew);

    // 3 pull-style SpMM layers (4 rows/warp, LDG.128)
    k_gather<0><<<grid_gather, BLK>>>(out);
    k_gather<1><<<grid_gather, BLK>>>(out);
    k_gather<2><<<grid_gather, BLK>>>(out);
}